// round 11
// baseline (speedup 1.0000x reference)
#include <cuda_runtime.h>
#include <stdint.h>
#include <float.h>

#define P_TOTAL 80000
#define OUTC    64
#define XL      432
#define YL      496
#define BS      4
#define PLANE   (YL * XL)            // 214272
#define K1_BLOCKS 1184
#define K1_WARPS  (K1_BLOCKS * 8)

#define HCELLS  216                  // half a BEV row per k2 block
#define XG      (HCELLS / 4)         // 54 float4 groups per channel row
#define PITCH   220                  // tile row pitch in floats (880B, 16B-aligned)

// Scratch (device globals — no allocation allowed)
__device__ float g_pooled[P_TOTAL * OUTC];   // 20.5 MB, L2-resident
__device__ int   g_map[BS * YL * XL];        // inverse map, memset to -1

__device__ __forceinline__ uint64_t pack2s(float x) {
    uint64_t r; asm("mov.b64 %0, {%1,%1};" : "=l"(r) : "f"(x)); return r;
}
__device__ __forceinline__ uint64_t fma2(uint64_t a, uint64_t b, uint64_t c) {
    uint64_t d;
    asm("fma.rn.f32x2 %0, %1, %2, %3;" : "=l"(d) : "l"(a), "l"(b), "l"(c));
    return d;
}
__device__ __forceinline__ float2 unpack2(uint64_t v) {
    float2 f; asm("mov.b64 {%0,%1}, %2;" : "=f"(f.x), "=f"(f.y) : "l"(v)); return f;
}

// ---------------------------------------------------------------------------
// k1: grid-stride, one warp per pillar per iteration.
// Points staged pair-interleaved (32B per point-pair: x0x1 y0y1 z0z1 w0w1) in
// a double-buffered smem slab, so the inner loop reads one pair with two
// uniform-address LDS.128 broadcasts. Max accumulated on the unpacked halves
// (mov.b64 split is register renaming; FMNMX is the real op).
// ---------------------------------------------------------------------------
__global__ void __launch_bounds__(256) k1(
    const float4* __restrict__ pillars,
    const int*    __restrict__ npoints,
    const int4*   __restrict__ coors,
    const float*  __restrict__ conv_w,
    const float*  __restrict__ gamma,
    const float*  __restrict__ beta,
    const float*  __restrict__ mean,
    const float*  __restrict__ var)
{
    __shared__ float sW[10][OUTC];
    __shared__ float spair[8][2][16][8];   // [warp][buf][pair][8 floats]

    const int tid  = threadIdx.x;
    const int w    = tid >> 5;
    const int lane = tid & 31;

    if (tid < OUTC) {
        const int c = tid;
        const float a  = gamma[c] * rsqrtf(var[c] + 1e-3f);
        const float bb = beta[c] - mean[c] * a;
        float u[9];
#pragma unroll
        for (int k = 0; k < 9; k++) u[k] = conv_w[c * 9 + k] * a;
        sW[0][c] = u[0] + u[4] + u[7];
        sW[1][c] = u[1] + u[5] + u[8];
        sW[2][c] = u[2] + u[6];
        sW[3][c] = u[3];
        sW[4][c] = -u[4];
        sW[5][c] = -u[5];
        sW[6][c] = -u[6];
        sW[7][c] = -u[7];
        sW[8][c] = -u[8];
        sW[9][c] = bb;
    }
    __syncthreads();

    const int c0 = lane, c1 = lane + 32;
    const float w0a = sW[0][c0], w1a = sW[1][c0], w2a = sW[2][c0], w3a = sW[3][c0];
    const float w0b = sW[0][c1], w1b = sW[1][c1], w2b = sW[2][c1], w3b = sW[3][c1];
    const uint64_t W0a = pack2s(w0a), W1a = pack2s(w1a);
    const uint64_t W2a = pack2s(w2a), W3a = pack2s(w3a);
    const uint64_t W0b = pack2s(w0b), W1b = pack2s(w1b);
    const uint64_t W2b = pack2s(w2b), W3b = pack2s(w3b);
    const float n4a = sW[4][c0], n5a = sW[5][c0], n6a = sW[6][c0];
    const float n7a = sW[7][c0], n8a = sW[8][c0], bba = sW[9][c0];
    const float n4b = sW[4][c1], n5b = sW[5][c1], n6b = sW[6][c1];
    const float n7b = sW[7][c1], n8b = sW[8][c1], bbb = sW[9][c1];

    const int gw = (blockIdx.x * 256 + tid) >> 5;
    const int j_st = lane >> 1, o_st = lane & 1;   // staging slot for this lane
    int buf = 0;

    for (int p = gw; p < P_TOTAL; p += K1_WARPS) {
        const float4 pt = pillars[p * 32 + lane];
        const int    np = npoints[p];
        const int4   cb = coors[p];

        // stage pair-interleaved: [x_2j, x_2j+1, y_2j, y_2j+1, z.., w..]
        {
            float* dst = &spair[w][buf][j_st][o_st];
            dst[0] = pt.x; dst[2] = pt.y; dst[4] = pt.z; dst[6] = pt.w;
        }

        float sx = pt.x, sy = pt.y, sz = pt.z;
#pragma unroll
        for (int o = 16; o > 0; o >>= 1) {
            sx += __shfl_xor_sync(0xFFFFFFFFu, sx, o);
            sy += __shfl_xor_sync(0xFFFFFFFFu, sy, o);
            sz += __shfl_xor_sync(0xFFFFFFFFu, sz, o);
        }

        __syncwarp();   // staging visible; also fences reads of this buf from 2 iters ago

        const float inv = __fdividef(1.0f, (float)np);
        const float mx = sx * inv, my = sy * inv, mz = sz * inv;
        const float cx = (float)cb.y * 0.16f + 0.08f;
        const float cy = (float)cb.z * 0.16f + (0.08f - 39.68f);

        float pc0 = bba, pc1 = bbb;
        pc0 = fmaf(n4a, mx, pc0);  pc1 = fmaf(n4b, mx, pc1);
        pc0 = fmaf(n5a, my, pc0);  pc1 = fmaf(n5b, my, pc1);
        pc0 = fmaf(n6a, mz, pc0);  pc1 = fmaf(n6b, mz, pc1);
        pc0 = fmaf(n7a, cx, pc0);  pc1 = fmaf(n7b, cx, pc1);
        pc0 = fmaf(n8a, cy, pc0);  pc1 = fmaf(n8b, cy, pc1);
        const uint64_t pcA = pack2s(pc0);
        const uint64_t pcB = pack2s(pc1);

        float m0 = -FLT_MAX, m1 = -FLT_MAX;
        const float* base = &spair[w][buf][0][0];
        const int npair = np >> 1;
#pragma unroll 2
        for (int q = 0; q < npair; q++) {
            const ulonglong2 xy = *(const ulonglong2*)(base + q * 8);      // x01, y01
            const ulonglong2 zw = *(const ulonglong2*)(base + q * 8 + 4);  // z01, w01
            uint64_t dA = pcA, dB = pcB;
            dA = fma2(xy.x, W0a, dA);  dB = fma2(xy.x, W0b, dB);
            dA = fma2(xy.y, W1a, dA);  dB = fma2(xy.y, W1b, dB);
            dA = fma2(zw.x, W2a, dA);  dB = fma2(zw.x, W2b, dB);
            dA = fma2(zw.y, W3a, dA);  dB = fma2(zw.y, W3b, dB);
            const float2 va = unpack2(dA);   // register renaming, no ALU op
            const float2 vb = unpack2(dB);
            m0 = fmaxf(m0, fmaxf(va.x, va.y));
            m1 = fmaxf(m1, fmaxf(vb.x, vb.y));
        }

        if (np & 1) {                 // odd np: last point is at pair np>>1, slot 0
            const float* tp = base + (np >> 1) * 8;
            const float f0 = tp[0], f1 = tp[2], f2 = tp[4], f3 = tp[6];
            float d0 = pc0, d1 = pc1;
            d0 = fmaf(f0, w0a, d0);  d1 = fmaf(f0, w0b, d1);
            d0 = fmaf(f1, w1a, d0);  d1 = fmaf(f1, w1b, d1);
            d0 = fmaf(f2, w2a, d0);  d1 = fmaf(f2, w2b, d1);
            d0 = fmaf(f3, w3a, d0);  d1 = fmaf(f3, w3b, d1);
            m0 = fmaxf(m0, d0);
            m1 = fmaxf(m1, d1);
        }
        if (np < 32) { m0 = fmaxf(m0, bba); m1 = fmaxf(m1, bbb); }  // masked pts => bias
        m0 = fmaxf(m0, 0.0f);
        m1 = fmaxf(m1, 0.0f);

        g_pooled[p * OUTC + c0] = m0;                 // coalesced
        g_pooled[p * OUTC + c1] = m1;
        if (lane == 0)
            g_map[(cb.x * YL + cb.z) * XL + cb.y] = p;

        buf ^= 1;
    }
}

// ---------------------------------------------------------------------------
// k2: block = half a BEV row (216 cells). 4 passes x 16 channels through a
// channel-major smem tile.
//  Phase 1: 4 lanes per cell fetch one 64B chunk of the pillar row (single
//           128B line -> 8 wavefronts/warp-instr instead of 32), scatter into
//           tile[channel][cell] (2-way STS conflict worst case).
//  Phase 2: LDS.128 from tile rows, fully-coalesced streaming STG.128 to the
//           channel planes. Empty cells emit zeros (no 219MB memset needed).
// ---------------------------------------------------------------------------
__global__ void __launch_bounds__(256) k2(float* __restrict__ out)
{
    __shared__ int   sidx[HCELLS];
    __shared__ float tile[16 * PITCH];     // 14080 B

    const int tid  = threadIdx.x;
    const int half = blockIdx.x & 1;
    const int row  = blockIdx.x >> 1;      // 0..BS*YL-1
    const int b = row / YL;
    const int y = row - b * YL;
    const int x0 = half * HCELLS;

    if (tid < HCELLS) sidx[tid] = g_map[row * XL + x0 + tid];
    __syncthreads();

    float* const obase = out + ((size_t)b * OUTC * YL + y) * XL + x0;

#pragma unroll
    for (int pass = 0; pass < 4; pass++) {
        // phase 1: gather channels [16*pass, 16*pass+16) for all 216 cells
        for (int idx = tid; idx < HCELLS * 4; idx += 256) {
            const int cell = idx >> 2;
            const int f    = idx & 3;
            const int pid  = sidx[cell];
            float4 v = make_float4(0.f, 0.f, 0.f, 0.f);
            if (pid >= 0)
                v = __ldg((const float4*)(g_pooled + pid * OUTC) + pass * 4 + f);
            float* t = tile + (4 * f) * PITCH + cell;
            t[0 * PITCH] = v.x;
            t[1 * PITCH] = v.y;
            t[2 * PITCH] = v.z;
            t[3 * PITCH] = v.w;
        }
        __syncthreads();

        // phase 2: 16 channel rows x 54 float4 coalesced streaming stores
        for (int idx = tid; idx < 16 * XG; idx += 256) {
            const int c  = idx / XG;
            const int xg = idx - c * XG;
            const float4 v = *(const float4*)(tile + c * PITCH + xg * 4);
            __stcs((float4*)(obase + (size_t)(16 * pass + c) * PLANE + xg * 4), v);
        }
        __syncthreads();
    }
}

extern "C" void kernel_launch(void* const* d_in, const int* in_sizes, int n_in,
                              void* d_out, int out_size) {
    const float4* pillars  = (const float4*)d_in[0];
    const int*    npoints  = (const int*)d_in[1];
    const int4*   coors    = (const int4*)d_in[2];
    const float*  conv_w   = (const float*)d_in[3];
    const float*  bn_gamma = (const float*)d_in[4];
    const float*  bn_beta  = (const float*)d_in[5];
    const float*  bn_mean  = (const float*)d_in[6];
    const float*  bn_var   = (const float*)d_in[7];
    float* out = (float*)d_out;

    void* map_ptr = nullptr;
    cudaGetSymbolAddress(&map_ptr, g_map);
    cudaMemsetAsync(map_ptr, 0xFF, sizeof(int) * BS * YL * XL);   // map = -1

    k1<<<K1_BLOCKS, 256>>>(pillars, npoints, coors, conv_w,
                           bn_gamma, bn_beta, bn_mean, bn_var);
    k2<<<BS * YL * 2, 256>>>(out);
}

// round 12
// speedup vs baseline: 1.0426x; 1.0426x over previous
#include <cuda_runtime.h>
#include <stdint.h>
#include <float.h>

#define P_TOTAL 80000
#define OUTC    64
#define XL      432
#define YL      496
#define BS      4
#define PLANE   (YL * XL)            // 214272
#define K1_BLOCKS 1184
#define K1_WARPS  (K1_BLOCKS * 8)

#define XG_ROW  (XL / 4)             // 108 float4 groups per row
#define K2_ITEMS (BS * YL * XG_ROW)  // 214272 work items
#define K2_BLOCKS (K2_ITEMS / 256)   // 837 exactly

// Scratch (device globals — no allocation allowed)
__device__ float g_pooled[P_TOTAL * OUTC];   // 20.5 MB, L2-resident
__device__ int   g_map[BS * YL * XL];        // inverse map, memset to -1

__device__ __forceinline__ uint64_t pack2s(float x) {
    uint64_t r; asm("mov.b64 %0, {%1,%1};" : "=l"(r) : "f"(x)); return r;
}
__device__ __forceinline__ uint64_t fma2(uint64_t a, uint64_t b, uint64_t c) {
    uint64_t d;
    asm("fma.rn.f32x2 %0, %1, %2, %3;" : "=l"(d) : "l"(a), "l"(b), "l"(c));
    return d;
}
__device__ __forceinline__ float2 unpack2(uint64_t v) {
    float2 f; asm("mov.b64 {%0,%1}, %2;" : "=f"(f.x), "=f"(f.y) : "l"(v)); return f;
}

// ---------------------------------------------------------------------------
// k1: grid-stride, one warp per pillar per iteration.
// Points staged pair-interleaved (32B per point-pair: x0x1 y0y1 z0z1 w0w1) in
// a double-buffered smem slab; inner loop reads one pair with two
// uniform-address LDS.128 broadcasts and does 8 packed fma.rn.f32x2.
// ---------------------------------------------------------------------------
__global__ void __launch_bounds__(256) k1(
    const float4* __restrict__ pillars,
    const int*    __restrict__ npoints,
    const int4*   __restrict__ coors,
    const float*  __restrict__ conv_w,
    const float*  __restrict__ gamma,
    const float*  __restrict__ beta,
    const float*  __restrict__ mean,
    const float*  __restrict__ var)
{
    __shared__ float sW[10][OUTC];
    __shared__ float spair[8][2][16][8];   // [warp][buf][pair][8 floats]

    const int tid  = threadIdx.x;
    const int w    = tid >> 5;
    const int lane = tid & 31;

    if (tid < OUTC) {
        const int c = tid;
        const float a  = gamma[c] * rsqrtf(var[c] + 1e-3f);
        const float bb = beta[c] - mean[c] * a;
        float u[9];
#pragma unroll
        for (int k = 0; k < 9; k++) u[k] = conv_w[c * 9 + k] * a;
        sW[0][c] = u[0] + u[4] + u[7];
        sW[1][c] = u[1] + u[5] + u[8];
        sW[2][c] = u[2] + u[6];
        sW[3][c] = u[3];
        sW[4][c] = -u[4];
        sW[5][c] = -u[5];
        sW[6][c] = -u[6];
        sW[7][c] = -u[7];
        sW[8][c] = -u[8];
        sW[9][c] = bb;
    }
    __syncthreads();

    const int c0 = lane, c1 = lane + 32;
    const float w0a = sW[0][c0], w1a = sW[1][c0], w2a = sW[2][c0], w3a = sW[3][c0];
    const float w0b = sW[0][c1], w1b = sW[1][c1], w2b = sW[2][c1], w3b = sW[3][c1];
    const uint64_t W0a = pack2s(w0a), W1a = pack2s(w1a);
    const uint64_t W2a = pack2s(w2a), W3a = pack2s(w3a);
    const uint64_t W0b = pack2s(w0b), W1b = pack2s(w1b);
    const uint64_t W2b = pack2s(w2b), W3b = pack2s(w3b);
    const float n4a = sW[4][c0], n5a = sW[5][c0], n6a = sW[6][c0];
    const float n7a = sW[7][c0], n8a = sW[8][c0], bba = sW[9][c0];
    const float n4b = sW[4][c1], n5b = sW[5][c1], n6b = sW[6][c1];
    const float n7b = sW[7][c1], n8b = sW[8][c1], bbb = sW[9][c1];

    const int gw = (blockIdx.x * 256 + tid) >> 5;
    const int j_st = lane >> 1, o_st = lane & 1;   // staging slot for this lane
    int buf = 0;

    for (int p = gw; p < P_TOTAL; p += K1_WARPS) {
        const float4 pt = pillars[p * 32 + lane];
        const int    np = npoints[p];
        const int4   cb = coors[p];

        // stage pair-interleaved: [x_2j, x_2j+1, y_2j, y_2j+1, z.., w..]
        {
            float* dst = &spair[w][buf][j_st][o_st];
            dst[0] = pt.x; dst[2] = pt.y; dst[4] = pt.z; dst[6] = pt.w;
        }

        float sx = pt.x, sy = pt.y, sz = pt.z;
#pragma unroll
        for (int o = 16; o > 0; o >>= 1) {
            sx += __shfl_xor_sync(0xFFFFFFFFu, sx, o);
            sy += __shfl_xor_sync(0xFFFFFFFFu, sy, o);
            sz += __shfl_xor_sync(0xFFFFFFFFu, sz, o);
        }

        __syncwarp();   // staging visible; also fences reads of this buf from 2 iters ago

        const float inv = __fdividef(1.0f, (float)np);
        const float mx = sx * inv, my = sy * inv, mz = sz * inv;
        const float cx = (float)cb.y * 0.16f + 0.08f;
        const float cy = (float)cb.z * 0.16f + (0.08f - 39.68f);

        float pc0 = bba, pc1 = bbb;
        pc0 = fmaf(n4a, mx, pc0);  pc1 = fmaf(n4b, mx, pc1);
        pc0 = fmaf(n5a, my, pc0);  pc1 = fmaf(n5b, my, pc1);
        pc0 = fmaf(n6a, mz, pc0);  pc1 = fmaf(n6b, mz, pc1);
        pc0 = fmaf(n7a, cx, pc0);  pc1 = fmaf(n7b, cx, pc1);
        pc0 = fmaf(n8a, cy, pc0);  pc1 = fmaf(n8b, cy, pc1);
        const uint64_t pcA = pack2s(pc0);
        const uint64_t pcB = pack2s(pc1);

        float m0 = -FLT_MAX, m1 = -FLT_MAX;
        const float* base = &spair[w][buf][0][0];
        const int npair = np >> 1;
#pragma unroll 2
        for (int q = 0; q < npair; q++) {
            const ulonglong2 xy = *(const ulonglong2*)(base + q * 8);      // x01, y01
            const ulonglong2 zw = *(const ulonglong2*)(base + q * 8 + 4);  // z01, w01
            uint64_t dA = pcA, dB = pcB;
            dA = fma2(xy.x, W0a, dA);  dB = fma2(xy.x, W0b, dB);
            dA = fma2(xy.y, W1a, dA);  dB = fma2(xy.y, W1b, dB);
            dA = fma2(zw.x, W2a, dA);  dB = fma2(zw.x, W2b, dB);
            dA = fma2(zw.y, W3a, dA);  dB = fma2(zw.y, W3b, dB);
            const float2 va = unpack2(dA);   // register renaming, no ALU op
            const float2 vb = unpack2(dB);
            m0 = fmaxf(m0, fmaxf(va.x, va.y));
            m1 = fmaxf(m1, fmaxf(vb.x, vb.y));
        }

        if (np & 1) {                 // odd np: last point is at pair np>>1, slot 0
            const float* tp = base + (np >> 1) * 8;
            const float f0 = tp[0], f1 = tp[2], f2 = tp[4], f3 = tp[6];
            float d0 = pc0, d1 = pc1;
            d0 = fmaf(f0, w0a, d0);  d1 = fmaf(f0, w0b, d1);
            d0 = fmaf(f1, w1a, d0);  d1 = fmaf(f1, w1b, d1);
            d0 = fmaf(f2, w2a, d0);  d1 = fmaf(f2, w2b, d1);
            d0 = fmaf(f3, w3a, d0);  d1 = fmaf(f3, w3b, d1);
            m0 = fmaxf(m0, d0);
            m1 = fmaxf(m1, d1);
        }
        if (np < 32) { m0 = fmaxf(m0, bba); m1 = fmaxf(m1, bbb); }  // masked pts => bias
        m0 = fmaxf(m0, 0.0f);
        m1 = fmaxf(m1, 0.0f);

        g_pooled[p * OUTC + c0] = m0;                 // coalesced
        g_pooled[p * OUTC + c1] = m1;
        if (lane == 0)
            g_map[(cb.x * YL + cb.z) * XL + cb.y] = p;

        buf ^= 1;
    }
}

// ---------------------------------------------------------------------------
// k2 (R8 dataflow, higher occupancy): one work item = (row, 4 consecutive x
// cells). Thread reads its 4 pillar ids as one int4 (rows are 16B-aligned:
// 432*4B=1728B), gathers 4 channels per pillar with LDG.128 from L2-resident
// g_pooled (only ~9% of cells are non-empty), transposes in registers, and
// writes one streaming STG.128 per channel row. 256-thread blocks + bounded
// unroll keep regs low for ~2x the resident warps of the 448-thread version.
// ---------------------------------------------------------------------------
__global__ void __launch_bounds__(256) k2(float* __restrict__ out)
{
    const int item = blockIdx.x * 256 + threadIdx.x;   // 0..214271
    const int row  = item / XG_ROW;                    // 0..1983
    const int xg   = item - row * XG_ROW;              // 0..107
    const int b = row / YL;
    const int y = row - b * YL;

    const int4 pid = *(const int4*)(g_map + row * XL + xg * 4);

    const float4* s0 = (const float4*)(g_pooled + (pid.x < 0 ? 0 : pid.x) * OUTC);
    const float4* s1 = (const float4*)(g_pooled + (pid.y < 0 ? 0 : pid.y) * OUTC);
    const float4* s2 = (const float4*)(g_pooled + (pid.z < 0 ? 0 : pid.z) * OUTC);
    const float4* s3 = (const float4*)(g_pooled + (pid.w < 0 ? 0 : pid.w) * OUTC);

    float* op = out + ((size_t)b * OUTC * YL + y) * XL + xg * 4;   // c=0 plane

    const float4 z4 = make_float4(0.f, 0.f, 0.f, 0.f);
#pragma unroll 4
    for (int cg = 0; cg < 16; cg++) {
        const float4 v0 = (pid.x >= 0) ? __ldg(s0 + cg) : z4;
        const float4 v1 = (pid.y >= 0) ? __ldg(s1 + cg) : z4;
        const float4 v2 = (pid.z >= 0) ? __ldg(s2 + cg) : z4;
        const float4 v3 = (pid.w >= 0) ? __ldg(s3 + cg) : z4;
        __stcs((float4*)(op + (size_t)(4 * cg + 0) * PLANE),
               make_float4(v0.x, v1.x, v2.x, v3.x));
        __stcs((float4*)(op + (size_t)(4 * cg + 1) * PLANE),
               make_float4(v0.y, v1.y, v2.y, v3.y));
        __stcs((float4*)(op + (size_t)(4 * cg + 2) * PLANE),
               make_float4(v0.z, v1.z, v2.z, v3.z));
        __stcs((float4*)(op + (size_t)(4 * cg + 3) * PLANE),
               make_float4(v0.w, v1.w, v2.w, v3.w));
    }
}

extern "C" void kernel_launch(void* const* d_in, const int* in_sizes, int n_in,
                              void* d_out, int out_size) {
    const float4* pillars  = (const float4*)d_in[0];
    const int*    npoints  = (const int*)d_in[1];
    const int4*   coors    = (const int4*)d_in[2];
    const float*  conv_w   = (const float*)d_in[3];
    const float*  bn_gamma = (const float*)d_in[4];
    const float*  bn_beta  = (const float*)d_in[5];
    const float*  bn_mean  = (const float*)d_in[6];
    const float*  bn_var   = (const float*)d_in[7];
    float* out = (float*)d_out;

    void* map_ptr = nullptr;
    cudaGetSymbolAddress(&map_ptr, g_map);
    cudaMemsetAsync(map_ptr, 0xFF, sizeof(int) * BS * YL * XL);   // map = -1

    k1<<<K1_BLOCKS, 256>>>(pillars, npoints, coors, conv_w,
                           bn_gamma, bn_beta, bn_mean, bn_var);
    k2<<<K2_BLOCKS, 256>>>(out);
}